// round 7
// baseline (speedup 1.0000x reference)
#include <cuda_runtime.h>

// Problem constants
#define Bb 4
#define Ff 5
#define Nn 2048
#define Dd 256
#define BFc (Bb*Ff)          // 20 frames
#define BFN (BFc*Nn)         // 40960
#define BFD (BFc*Dd)         // 5120
#define POSINF_BITS 0x7F800000

// ---- scratch (no allocations allowed -> device globals) ----
__device__ int      g_rowmin[BFN];   // float bits, min over m of d[n,m]
__device__ int      g_colmin[BFN];   // float bits, min over n of d[n,m]
__device__ float    g_x2[BFN];
__device__ float    g_y2[BFN];
__device__ unsigned g_mnx[BFD], g_mxx[BFD], g_mny[BFD], g_mxy[BFD];
__device__ float    g_wx[Bb], g_wy[Bb];
__device__ float    g_sx[BFD], g_sy[BFD], g_of[BFD];

// monotonic unsigned encoding of float (total order incl. negatives)
__device__ __forceinline__ unsigned encf(float f) {
    unsigned u = __float_as_uint(f);
    return (u & 0x80000000u) ? ~u : (u | 0x80000000u);
}
__device__ __forceinline__ float decf(unsigned e) {
    unsigned u = (e & 0x80000000u) ? (e ^ 0x80000000u) : ~e;
    return __uint_as_float(u);
}

// ---- reset accumulators (must run every launch: graph replays) ----
__global__ void k_init() {
    int i = blockIdx.x * blockDim.x + threadIdx.x;
    if (i < BFN) { g_rowmin[i] = POSINF_BITS; g_colmin[i] = POSINF_BITS; }
    if (i < BFD) {
        g_mnx[i] = 0xFFFFFFFFu; g_mny[i] = 0xFFFFFFFFu;
        g_mxx[i] = 0u;          g_mxy[i] = 0u;
    }
}

// ---- squared row norms: one warp per row, float4 loads ----
__global__ __launch_bounds__(256) void k_norms(const float* __restrict__ x,
                                               const float* __restrict__ y) {
    int row  = blockIdx.x * 8 + (threadIdx.x >> 5);
    int lane = threadIdx.x & 31;
    const float4* xr = (const float4*)(x + (size_t)row * Dd);
    const float4* yr = (const float4*)(y + (size_t)row * Dd);
    float sx = 0.f, sy = 0.f;
#pragma unroll
    for (int i = 0; i < 2; i++) {
        float4 v = xr[lane + 32 * i];
        sx += v.x * v.x + v.y * v.y + v.z * v.z + v.w * v.w;
        float4 w = yr[lane + 32 * i];
        sy += w.x * w.x + w.y * w.y + w.z * w.z + w.w * w.w;
    }
#pragma unroll
    for (int o = 16; o; o >>= 1) {
        sx += __shfl_xor_sync(0xFFFFFFFFu, sx, o);
        sy += __shfl_xor_sync(0xFFFFFFFFu, sy, o);
    }
    if (lane == 0) { g_x2[row] = sx; g_y2[row] = sy; }
}

// ---- tiled distance kernel: 128x128 tile, 8x8 per thread, fused min-reduce ----
__global__ __launch_bounds__(256) void k_dist(const float* __restrict__ x,
                                              const float* __restrict__ y) {
    const int bf = blockIdx.y;
    const int nt = blockIdx.x >> 4;
    const int mt = blockIdx.x & 15;
    const int n0 = nt * 128, m0 = mt * 128;
    const float* xb = x + (size_t)bf * Nn * Dd;
    const float* yb = y + (size_t)bf * Nn * Dd;

    __shared__ float As[16][129];   // [k][n], padded
    __shared__ float Bs[16][129];   // [k][m], padded
    __shared__ int   s_row[128];
    __shared__ int   s_col[128];

    const int tid = threadIdx.x;
    const int tx = tid & 15, ty = tid >> 4;
    if (tid < 128) { s_row[tid] = POSINF_BITS; s_col[tid] = POSINF_BITS; }

    float acc[8][8];
#pragma unroll
    for (int i = 0; i < 8; i++)
#pragma unroll
        for (int j = 0; j < 8; j++) acc[i][j] = 0.f;

    const int lrow = tid >> 2;          // 0..63
    const int lk   = (tid & 3) << 2;    // 0,4,8,12

    for (int kc = 0; kc < Dd; kc += 16) {
        __syncthreads();   // protect smem from previous iteration's readers
#pragma unroll
        for (int r = 0; r < 2; r++) {
            int row = lrow + 64 * r;
            float4 v = *(const float4*)(xb + (size_t)(n0 + row) * Dd + kc + lk);
            As[lk + 0][row] = v.x; As[lk + 1][row] = v.y;
            As[lk + 2][row] = v.z; As[lk + 3][row] = v.w;
            float4 w = *(const float4*)(yb + (size_t)(m0 + row) * Dd + kc + lk);
            Bs[lk + 0][row] = w.x; Bs[lk + 1][row] = w.y;
            Bs[lk + 2][row] = w.z; Bs[lk + 3][row] = w.w;
        }
        __syncthreads();
#pragma unroll
        for (int k = 0; k < 16; k++) {
            float a[8], bv[8];
#pragma unroll
            for (int i = 0; i < 8; i++) a[i] = As[k][ty + 16 * i];
#pragma unroll
            for (int j = 0; j < 8; j++) bv[j] = Bs[k][tx + 16 * j];
#pragma unroll
            for (int i = 0; i < 8; i++)
#pragma unroll
                for (int j = 0; j < 8; j++)
                    acc[i][j] = fmaf(a[i], bv[j], acc[i][j]);
        }
    }

    // epilogue: d = x2 + y2 - 2*dot, fused row/col min
    const int nb = bf * Nn + n0, mb = bf * Nn + m0;
    float x2r[8], y2c[8];
#pragma unroll
    for (int i = 0; i < 8; i++) x2r[i] = g_x2[nb + ty + 16 * i];
#pragma unroll
    for (int j = 0; j < 8; j++) y2c[j] = g_y2[mb + tx + 16 * j];

    const float INFF = __int_as_float(POSINF_BITS);
    float cmin[8];
#pragma unroll
    for (int j = 0; j < 8; j++) cmin[j] = INFF;
#pragma unroll
    for (int i = 0; i < 8; i++) {
        float rm = INFF;
#pragma unroll
        for (int j = 0; j < 8; j++) {
            float dv = x2r[i] + y2c[j] - 2.f * acc[i][j];
            rm = fminf(rm, dv);
            cmin[j] = fminf(cmin[j], dv);
        }
        atomicMin(&s_row[ty + 16 * i], __float_as_int(rm));
    }
#pragma unroll
    for (int j = 0; j < 8; j++)
        atomicMin(&s_col[tx + 16 * j], __float_as_int(cmin[j]));
    __syncthreads();
    if (tid < 128) {
        atomicMin(&g_rowmin[nb + tid], s_row[tid]);
        atomicMin(&g_colmin[mb + tid], s_col[tid]);
    }
}

// ---- reduce mins -> per-batch weights wx, wy ----
__global__ void k_wred() {
    int b = blockIdx.x;
    const int base = b * Ff * Nn;
    float sr = 0.f, sc = 0.f;
    for (int i = threadIdx.x; i < Ff * Nn; i += 256) {
        sr += __int_as_float(g_rowmin[base + i]);
        sc += __int_as_float(g_colmin[base + i]);
    }
    __shared__ float ssr[256], ssc[256];
    ssr[threadIdx.x] = sr; ssc[threadIdx.x] = sc;
    __syncthreads();
    for (int s = 128; s; s >>= 1) {
        if (threadIdx.x < s) {
            ssr[threadIdx.x] += ssr[threadIdx.x + s];
            ssc[threadIdx.x] += ssc[threadIdx.x + s];
        }
        __syncthreads();
    }
    if (threadIdx.x == 0) {
        g_wx[b] = 1.f / (1.f + ssr[0] / (float)(Ff * Nn));
        g_wy[b] = 1.f / (1.f + ssc[0] / (float)(Ff * Nn));
    }
}

// ---- per (bf,d) min/max over node dim, chunked over n ----
__global__ __launch_bounds__(256) void k_minmax(const float* __restrict__ x,
                                                const float* __restrict__ y) {
    int bf = blockIdx.x, c = blockIdx.y, d = threadIdx.x;
    const float* xp = x + ((size_t)bf * Nn + c * 128) * Dd + d;
    const float* yp = y + ((size_t)bf * Nn + c * 128) * Dd + d;
    const float INFF = __int_as_float(POSINF_BITS);
    float mnx = INFF, mxx = -INFF, mny = INFF, mxy = -INFF;
    for (int n = 0; n < 128; n++) {
        float vx = xp[(size_t)n * Dd];
        mnx = fminf(mnx, vx); mxx = fmaxf(mxx, vx);
        float vy = yp[(size_t)n * Dd];
        mny = fminf(mny, vy); mxy = fmaxf(mxy, vy);
    }
    int gi = bf * Dd + d;
    atomicMin(&g_mnx[gi], encf(mnx)); atomicMax(&g_mxx[gi], encf(mxx));
    atomicMin(&g_mny[gi], encf(mny)); atomicMax(&g_mxy[gi], encf(mxy));
}

// ---- fold weights + min/max into per-(bf,d) affine coefficients ----
__global__ void k_coef() {
    int i = blockIdx.x * blockDim.x + threadIdx.x;
    if (i >= BFD) return;
    int b = i / (Ff * Dd);
    float wx = g_wx[b], wy = g_wy[b];
    float mnx = decf(g_mnx[i]), mxx = decf(g_mxx[i]);
    float mny = decf(g_mny[i]), mxy = decf(g_mxy[i]);
    float sx = wx / (mxx - mnx);
    float sy = wy / (mxy - mny);
    g_sx[i] = sx; g_sy[i] = sy;
    g_of[i] = -mnx * sx - mny * sy;
}

// ---- final fused combine: out = x*sx + y*sy + off, float4 ----
__global__ __launch_bounds__(256) void k_combine(const float4* __restrict__ x,
                                                 const float4* __restrict__ y,
                                                 float4* __restrict__ out) {
    int idx = blockIdx.x * blockDim.x + threadIdx.x;
    const int total4 = Bb * Ff * Nn * Dd / 4;
    if (idx >= total4) return;
    int bf = idx / (Nn * Dd / 4);
    int d4 = idx & (Dd / 4 - 1);
    int ci = bf * (Dd / 4) + d4;
    float4 sx = ((const float4*)g_sx)[ci];
    float4 sy = ((const float4*)g_sy)[ci];
    float4 of = ((const float4*)g_of)[ci];
    float4 xv = x[idx], yv = y[idx];
    float4 o;
    o.x = fmaf(xv.x, sx.x, fmaf(yv.x, sy.x, of.x));
    o.y = fmaf(xv.y, sx.y, fmaf(yv.y, sy.y, of.y));
    o.z = fmaf(xv.z, sx.z, fmaf(yv.z, sy.z, of.z));
    o.w = fmaf(xv.w, sx.w, fmaf(yv.w, sy.w, of.w));
    out[idx] = o;
}

extern "C" void kernel_launch(void* const* d_in, const int* in_sizes, int n_in,
                              void* d_out, int out_size) {
    const float* x = (const float*)d_in[0];
    const float* y = (const float*)d_in[1];
    float* out = (float*)d_out;

    k_init<<<(BFN + 255) / 256, 256>>>();
    k_norms<<<BFN / 8, 256>>>(x, y);
    {
        dim3 gd(16 * 16, BFc);   // 256 tiles per frame, 20 frames
        k_dist<<<gd, 256>>>(x, y);
    }
    k_wred<<<Bb, 256>>>();
    {
        dim3 gm(BFc, Nn / 128);  // 20 frames x 16 n-chunks
        k_minmax<<<gm, 256>>>(x, y);
    }
    k_coef<<<(BFD + 255) / 256, 256>>>();
    {
        const int total4 = Bb * Ff * Nn * Dd / 4;
        k_combine<<<(total4 + 255) / 256, 256>>>((const float4*)x,
                                                 (const float4*)y,
                                                 (float4*)out);
    }
}